// round 8
// baseline (speedup 1.0000x reference)
#include <cuda_runtime.h>

#define NMAX 100000
#define EMAXN 1600000
#define SCB 512                 // scan block size

// ---- scratch (device globals). 16B-aligned for vector access ----
__device__ __align__(16) float g_xw[NMAX * 64];     // [N][64]: 0..31 x@W_rel1, 32..63 x@W_root1
__device__ __align__(16) float g_sum1[NMAX * 32];
__device__ __align__(16) float g_hr[NMAX * 8];      // h@W_rel2 (pad 8)
__device__ __align__(16) float g_hroot[NMAX * 8];   // h@W_root2 (pad 8)
__device__ __align__(16) float g_sum2[NMAX * 8];
__device__ __align__(16) int   g_src[EMAXN];
__device__ __align__(16) int   g_dst[EMAXN];
__device__ __align__(16) int   g_es[EMAXN];         // CSR: src sorted by dst
__device__ __align__(16) float g_ews[EMAXN];        // CSR: weight sorted by dst
__device__ int   g_deg[NMAX];
__device__ int   g_rs[NMAX];                        // CSR row start (exclusive scan)
__device__ int   g_cur[NMAX];
__device__ int   g_bs[1024];                        // scan partials
__device__ int   g_bso[1024];                       // scan partial offsets (exclusive)
__device__ int   g_is64;

// ---- helpers ----
__device__ __forceinline__ void ffma2(unsigned long long& d, unsigned long long a, unsigned long long b) {
    asm("fma.rn.f32x2 %0, %1, %2, %0;" : "+l"(d) : "l"(a), "l"(b));
}
__device__ __forceinline__ unsigned long long dup2(float a) {
    unsigned long long r;
    asm("mov.b64 %0, {%1, %1};" : "=l"(r) : "f"(a));
    return r;
}
__device__ __forceinline__ float2 u2f2(unsigned long long u) {
    float2 f;
    asm("mov.b64 {%0, %1}, %2;" : "=f"(f.x), "=f"(f.y) : "l"(u));
    return f;
}

// ---- detect int64 vs int32 edge_index ----
__global__ void k_detect(const int* __restrict__ ei) {
    int lane = threadIdx.x;          // 64 threads
    int nz = 0;
    for (int i = lane * 2 + 1; i < 256; i += 128) nz |= ei[i];
    __shared__ unsigned s[2];
    unsigned m = __ballot_sync(0xffffffff, nz != 0);
    s[lane >> 5] = m;
    __syncthreads();
    if (lane == 0) g_is64 = ((s[0] | s[1]) == 0);
}

// ---- zero small int arrays (deg, cursor) ----
__global__ void k_zero(int N) {
    int i = blockIdx.x * blockDim.x + threadIdx.x;
    if (i < N) { g_deg[i] = 0; g_cur[i] = 0; }
}

// ---- unpack indices + degree histogram ----
__global__ void __launch_bounds__(256) k_unpack(const int* __restrict__ ei, int E, int N) {
    int e = blockIdx.x * 256 + threadIdx.x;
    if (e >= E) return;
    int s, d;
    if (g_is64) { s = ei[2 * e];  d = ei[2 * E + 2 * e]; }
    else        { s = ei[e];      d = ei[E + e]; }
    if (s < 0 || s >= N) s = 0;
    if (d < 0 || d >= N) d = 0;
    g_src[e] = s;
    g_dst[e] = d;
    atomicAdd(&g_deg[d], 1);
}

// ---- scan step 1: per-block inclusive scan of deg ----
__global__ void __launch_bounds__(SCB) k_scan1(int N) {
    __shared__ int s[SCB];
    int t = threadIdx.x;
    int i = blockIdx.x * SCB + t;
    int v = (i < N) ? g_deg[i] : 0;
    s[t] = v;
    __syncthreads();
    #pragma unroll
    for (int off = 1; off < SCB; off <<= 1) {
        int add = (t >= off) ? s[t - off] : 0;
        __syncthreads();
        s[t] += add;
        __syncthreads();
    }
    if (i < N) g_rs[i] = s[t];                 // local inclusive
    if (t == SCB - 1) g_bs[blockIdx.x] = s[t];
}

// ---- scan step 2: exclusive scan of block totals (single block) ----
__global__ void __launch_bounds__(SCB) k_scan2(int nb) {
    __shared__ int s[SCB];
    int t = threadIdx.x;
    int v = (t < nb) ? g_bs[t] : 0;
    s[t] = v;
    __syncthreads();
    #pragma unroll
    for (int off = 1; off < SCB; off <<= 1) {
        int add = (t >= off) ? s[t - off] : 0;
        __syncthreads();
        s[t] += add;
        __syncthreads();
    }
    g_bso[t] = s[t] - v;                        // exclusive
}

// ---- scan step 3: finalize exclusive global row starts ----
__global__ void __launch_bounds__(256) k_scan3(int N) {
    int i = blockIdx.x * 256 + threadIdx.x;
    if (i < N) g_rs[i] = g_rs[i] - g_deg[i] + g_bso[i / SCB];
}

// ---- scatter edges into CSR order ----
__global__ void __launch_bounds__(256) k_scatter(const float* __restrict__ ew, int E) {
    int e = blockIdx.x * 256 + threadIdx.x;
    if (e >= E) return;
    int d = g_dst[e];
    int pos = g_rs[d] + atomicAdd(&g_cur[d], 1);
    g_es[pos]  = g_src[e];
    g_ews[pos] = ew[e];
}

// ---- K1: fused projection  g_xw = x @ [W_rel1 | W_root1]  (128 -> 64), f32x2 ----
// 128-node x 64-col tile, 256 threads, thread = 4 nodes x 8 cols.
__global__ void __launch_bounds__(256, 2) k_gemm1(
    const float* __restrict__ x,
    const float* __restrict__ Wrel,
    const float* __restrict__ Wroot,
    int N)
{
    extern __shared__ float sm[];
    float* Ws = sm;            // [64 k][64 c]    (4096 floats)
    float* Xs = sm + 4096;     // [128 node][70]  (pitch 70, even for float2)

    const int t  = threadIdx.x;
    const int tx = t & 7;      // col group: cols tx*8 .. +7
    const int ty = t >> 3;     // node group: nodes ty*4 .. +3
    const int n0 = blockIdx.x * 128;

    unsigned long long acc[4][4];
    #pragma unroll
    for (int i = 0; i < 4; i++)
        #pragma unroll
        for (int j = 0; j < 4; j++) acc[i][j] = 0ull;

    for (int kc = 0; kc < 128; kc += 64) {
        #pragma unroll
        for (int i = t; i < 4096; i += 256) {
            int kk = i >> 6, col = i & 63;
            Ws[i] = (col < 32) ? Wrel[(kc + kk) * 32 + col]
                               : Wroot[(kc + kk) * 32 + (col - 32)];
        }
        #pragma unroll
        for (int j = 0; j < 8; j++) {
            int idx  = t + 256 * j;          // 0..2047 float4 slots
            int kq   = idx & 15;
            int node = idx >> 4;
            int gn   = n0 + node;
            float4 v = (gn < N) ? *(const float4*)&x[gn * 128 + kc + kq * 4]
                                : make_float4(0.f, 0.f, 0.f, 0.f);
            float* dst = &Xs[node * 70 + kq * 4];
            dst[0] = v.x; dst[1] = v.y; dst[2] = v.z; dst[3] = v.w;
        }
        __syncthreads();

        const float* xrow = &Xs[(ty * 4) * 70];
        #pragma unroll 2
        for (int kk = 0; kk < 64; kk += 2) {
            ulonglong2 a01 = *(const ulonglong2*)&Ws[kk * 64 + tx * 8];
            ulonglong2 a23 = *(const ulonglong2*)&Ws[kk * 64 + tx * 8 + 4];
            ulonglong2 b01 = *(const ulonglong2*)&Ws[(kk + 1) * 64 + tx * 8];
            ulonglong2 b23 = *(const ulonglong2*)&Ws[(kk + 1) * 64 + tx * 8 + 4];
            #pragma unroll
            for (int i = 0; i < 4; i++) {
                float2 xp = *(const float2*)&xrow[i * 70 + kk];
                unsigned long long ax = dup2(xp.x);
                unsigned long long ay = dup2(xp.y);
                ffma2(acc[i][0], ax, a01.x);
                ffma2(acc[i][1], ax, a01.y);
                ffma2(acc[i][2], ax, a23.x);
                ffma2(acc[i][3], ax, a23.y);
                ffma2(acc[i][0], ay, b01.x);
                ffma2(acc[i][1], ay, b01.y);
                ffma2(acc[i][2], ay, b23.x);
                ffma2(acc[i][3], ay, b23.y);
            }
        }
        __syncthreads();
    }

    #pragma unroll
    for (int i = 0; i < 4; i++) {
        int node = n0 + ty * 4 + i;
        if (node < N) {
            float2 p0 = u2f2(acc[i][0]), p1 = u2f2(acc[i][1]);
            float2 p2 = u2f2(acc[i][2]), p3 = u2f2(acc[i][3]);
            *(float4*)&g_xw[node * 64 + tx * 8]     = make_float4(p0.x, p0.y, p1.x, p1.y);
            *(float4*)&g_xw[node * 64 + tx * 8 + 4] = make_float4(p2.x, p2.y, p3.x, p3.y);
        }
    }
}

// ---- edge pass 1 (CSR, no atomics): warp per node, lane = feature col ----
__global__ void __launch_bounds__(256) k_edge1_csr(int N) {
    int node = blockIdx.x * 8 + (threadIdx.x >> 5);
    int lane = threadIdx.x & 31;
    if (node >= N) return;
    int beg = g_rs[node];
    int end = beg + g_deg[node];
    float a0 = 0.f, a1 = 0.f, a2 = 0.f, a3 = 0.f;
    int j = beg;
    for (; j + 4 <= end; j += 4) {
        int   s0 = g_es[j],     s1 = g_es[j + 1], s2 = g_es[j + 2], s3 = g_es[j + 3];
        float w0 = g_ews[j],    w1 = g_ews[j + 1], w2 = g_ews[j + 2], w3 = g_ews[j + 3];
        a0 += w0 * g_xw[s0 * 64 + lane];
        a1 += w1 * g_xw[s1 * 64 + lane];
        a2 += w2 * g_xw[s2 * 64 + lane];
        a3 += w3 * g_xw[s3 * 64 + lane];
    }
    for (; j < end; j++) {
        a0 += g_ews[j] * g_xw[g_es[j] * 64 + lane];
    }
    g_sum1[node * 32 + lane] = (a0 + a1) + (a2 + a3);
}

// ---- combine layer 1 + project layer 2 ----
__global__ void __launch_bounds__(256) k_comb1(
    const float* __restrict__ b1,
    const float* __restrict__ Wrel2,    // [32][5]
    const float* __restrict__ Wroot2,   // [32][5]
    int N)
{
    __shared__ float sW[352];  // [0..159]=Wrel2, [160..319]=Wroot2, [320..351]=b1
    int t = threadIdx.x;
    for (int i = t; i < 352; i += 256) {
        sW[i] = (i < 160) ? Wrel2[i]
              : (i < 320) ? Wroot2[i - 160]
                          : b1[i - 320];
    }
    __syncthreads();

    int node = blockIdx.x * 256 + t;
    if (node >= N) return;

    float inv = 1.0f / fmaxf((float)g_deg[node], 1.0f);
    const float4* sp = (const float4*)&g_sum1[node * 32];
    const float4* rp = (const float4*)&g_xw[node * 64 + 32];

    float h[32];
    #pragma unroll
    for (int q = 0; q < 8; q++) {
        float4 s4 = sp[q];
        float4 r4 = rp[q];
        h[4 * q + 0] = fmaxf(s4.x * inv + r4.x + sW[320 + 4 * q + 0], 0.f);
        h[4 * q + 1] = fmaxf(s4.y * inv + r4.y + sW[320 + 4 * q + 1], 0.f);
        h[4 * q + 2] = fmaxf(s4.z * inv + r4.z + sW[320 + 4 * q + 2], 0.f);
        h[4 * q + 3] = fmaxf(s4.w * inv + r4.w + sW[320 + 4 * q + 3], 0.f);
    }

    float hr[5] = {0.f, 0.f, 0.f, 0.f, 0.f};
    float ho[5] = {0.f, 0.f, 0.f, 0.f, 0.f};
    #pragma unroll
    for (int j = 0; j < 32; j++) {
        float hv = h[j];
        #pragma unroll
        for (int c = 0; c < 5; c++) {
            hr[c] += hv * sW[j * 5 + c];
            ho[c] += hv * sW[160 + j * 5 + c];
        }
    }
    *(float4*)&g_hr[node * 8 + 0]    = make_float4(hr[0], hr[1], hr[2], hr[3]);
    *(float4*)&g_hr[node * 8 + 4]    = make_float4(hr[4], 0.f, 0.f, 0.f);
    *(float4*)&g_hroot[node * 8 + 0] = make_float4(ho[0], ho[1], ho[2], ho[3]);
    *(float4*)&g_hroot[node * 8 + 4] = make_float4(ho[4], 0.f, 0.f, 0.f);
}

// ---- edge pass 2 (CSR, no atomics): 8 lanes per node (cols 0..7, 5 real) ----
__global__ void __launch_bounds__(256) k_edge2_csr(int N) {
    int t = threadIdx.x;
    int node = blockIdx.x * 32 + (t >> 3);
    int c = t & 7;
    if (node >= N) return;
    int beg = g_rs[node];
    int end = beg + g_deg[node];
    float a0 = 0.f, a1 = 0.f, a2 = 0.f, a3 = 0.f;
    int j = beg;
    for (; j + 4 <= end; j += 4) {
        a0 += g_hr[g_es[j]     * 8 + c];
        a1 += g_hr[g_es[j + 1] * 8 + c];
        a2 += g_hr[g_es[j + 2] * 8 + c];
        a3 += g_hr[g_es[j + 3] * 8 + c];
    }
    for (; j < end; j++) a0 += g_hr[g_es[j] * 8 + c];
    g_sum2[node * 8 + c] = (a0 + a1) + (a2 + a3);
}

// ---- combine layer 2 + log_softmax ----
__global__ void __launch_bounds__(256) k_final(
    const float* __restrict__ b2,
    float* __restrict__ out,
    int N)
{
    int node = blockIdx.x * 256 + threadIdx.x;
    if (node >= N) return;
    float inv = 1.0f / fmaxf((float)g_deg[node], 1.0f);
    float v[5];
    #pragma unroll
    for (int c = 0; c < 5; c++)
        v[c] = g_sum2[node * 8 + c] * inv + g_hroot[node * 8 + c] + b2[c];

    float m = v[0];
    #pragma unroll
    for (int c = 1; c < 5; c++) m = fmaxf(m, v[c]);
    float sum = 0.f;
    #pragma unroll
    for (int c = 0; c < 5; c++) sum += expf(v[c] - m);
    float lse = m + logf(sum);
    #pragma unroll
    for (int c = 0; c < 5; c++) out[node * 5 + c] = v[c] - lse;
}

extern "C" void kernel_launch(void* const* d_in, const int* in_sizes, int n_in,
                              void* d_out, int out_size)
{
    const float* x      = (const float*)d_in[0];
    const int*   ei     = (const int*)d_in[1];
    const float* ew     = (const float*)d_in[2];
    const float* Wrel1  = (const float*)d_in[3];
    const float* Wroot1 = (const float*)d_in[4];
    const float* b1     = (const float*)d_in[5];
    const float* Wrel2  = (const float*)d_in[6];
    const float* Wroot2 = (const float*)d_in[7];
    const float* b2     = (const float*)d_in[8];
    float*       out    = (float*)d_out;

    int N  = out_size / 5;          // output [N,5]
    int E  = in_sizes[1] / 2;       // edge_index [2,E]
    int nb = (N + SCB - 1) / SCB;   // scan blocks

    const int GEMM_SMEM = (4096 + 128 * 70) * 4;   // 52224 B
    cudaFuncSetAttribute(k_gemm1, cudaFuncAttributeMaxDynamicSharedMemorySize, GEMM_SMEM);

    k_detect  <<<1, 64>>>(ei);
    k_zero    <<<(N + 255) / 256, 256>>>(N);
    k_unpack  <<<(E + 255) / 256, 256>>>(ei, E, N);
    k_gemm1   <<<(N + 127) / 128, 256, GEMM_SMEM>>>(x, Wrel1, Wroot1, N);
    k_scan1   <<<nb, SCB>>>(N);
    k_scan2   <<<1, SCB>>>(nb);
    k_scan3   <<<(N + 255) / 256, 256>>>(N);
    k_scatter <<<(E + 255) / 256, 256>>>(ew, E);
    k_edge1_csr<<<(N + 7) / 8, 256>>>(N);
    k_comb1   <<<(N + 255) / 256, 256>>>(b1, Wrel2, Wroot2, N);
    k_edge2_csr<<<(N + 31) / 32, 256>>>(N);
    k_final   <<<(N + 255) / 256, 256>>>(b2, out, N);
}

// round 9
// speedup vs baseline: 1.1545x; 1.1545x over previous
#include <cuda_runtime.h>

#define NMAX 100000
#define EMAXN 1600000

// ---- scratch (device globals). 16B-aligned for float4/RED.128 ----
__device__ __align__(16) float g_xw[NMAX * 64];     // [N][64]: 0..31 x@W_rel1, 32..63 x@W_root1
__device__ __align__(16) float g_sum1[NMAX * 32];
__device__ __align__(16) float g_cnt[NMAX];
__device__ __align__(16) float g_hr[NMAX * 8];      // h@W_rel2 (pad 8)
__device__ __align__(16) float g_hroot[NMAX * 8];   // h@W_root2 (pad 8)
__device__ __align__(16) float g_sum2[NMAX * 8];
__device__ __align__(16) int   g_src[EMAXN];
__device__ __align__(16) int   g_dst[EMAXN];
__device__ int g_is64;

// ---- helpers ----
__device__ __forceinline__ void ffma2(unsigned long long& d, unsigned long long a, unsigned long long b) {
    asm("fma.rn.f32x2 %0, %1, %2, %0;" : "+l"(d) : "l"(a), "l"(b));
}
__device__ __forceinline__ unsigned long long dup2(float a) {
    unsigned long long r;
    asm("mov.b64 %0, {%1, %1};" : "=l"(r) : "f"(a));
    return r;
}
__device__ __forceinline__ float2 u2f2(unsigned long long u) {
    float2 f;
    asm("mov.b64 {%0, %1}, %2;" : "=f"(f.x), "=f"(f.y) : "l"(u));
    return f;
}
__device__ __forceinline__ void red_add4(float* p, float4 v) {
    asm volatile("red.global.add.v4.f32 [%0], {%1,%2,%3,%4};"
                 :: "l"(p), "f"(v.x), "f"(v.y), "f"(v.z), "f"(v.w) : "memory");
}

// ---- detect int64 vs int32 edge_index ----
__global__ void k_detect(const int* __restrict__ ei) {
    int lane = threadIdx.x;          // 64 threads
    int nz = 0;
    for (int i = lane * 2 + 1; i < 256; i += 128) nz |= ei[i];
    __shared__ unsigned s[2];
    unsigned m = __ballot_sync(0xffffffff, nz != 0);
    s[lane >> 5] = m;
    __syncthreads();
    if (lane == 0) g_is64 = ((s[0] | s[1]) == 0);
}

// ---- zero accumulators (vectorized) ----
__global__ void k_zero(int N) {
    int i = blockIdx.x * blockDim.x + threadIdx.x;
    int stride = gridDim.x * blockDim.x;
    float4 z = make_float4(0.f, 0.f, 0.f, 0.f);
    for (int j = i; j < N * 8; j += stride) ((float4*)g_sum1)[j] = z;   // 32 floats/node
    for (int j = i; j < N * 2; j += stride) ((float4*)g_sum2)[j] = z;   // 8 floats/node
    for (int j = i; j < N;     j += stride) g_cnt[j] = 0.f;
}

// ---- unpack indices + degree count ----
__global__ void __launch_bounds__(256) k_unpack(const int* __restrict__ ei, int E, int N) {
    int e = blockIdx.x * 256 + threadIdx.x;
    if (e >= E) return;
    int s, d;
    if (g_is64) { s = ei[2 * e];  d = ei[2 * E + 2 * e]; }
    else        { s = ei[e];      d = ei[E + e]; }
    if (s < 0 || s >= N) s = 0;
    if (d < 0 || d >= N) d = 0;
    g_src[e] = s;
    g_dst[e] = d;
    atomicAdd(&g_cnt[d], 1.0f);
}

// ---- K1: fused projection  g_xw = x @ [W_rel1 | W_root1]  (128 -> 64), f32x2 ----
// 128 threads, 128-node x 64-col tile, thread = 8 nodes x 8 cols, kk unrolled x2.
// smem/FMA = 1.0 B; 4 CTAs/SM.
#define XPITCH 72
__global__ void __launch_bounds__(128, 4) k_gemm1(
    const float* __restrict__ x,
    const float* __restrict__ Wrel,
    const float* __restrict__ Wroot,
    int N)
{
    extern __shared__ float sm[];
    float* Ws = sm;              // [64 k][64 c]      (4096 floats)
    float* Xs = sm + 4096;       // [128 node][72]    (9216 floats)

    const int t  = threadIdx.x;
    const int tx = t & 7;        // col group: cols tx*8 .. +7
    const int ty = t >> 3;       // node group: nodes ty*8 .. +7
    const int n0 = blockIdx.x * 128;

    unsigned long long acc[8][4];
    #pragma unroll
    for (int i = 0; i < 8; i++)
        #pragma unroll
        for (int j = 0; j < 4; j++) acc[i][j] = 0ull;

    for (int kc = 0; kc < 128; kc += 64) {
        // stage W chunk [64 k][64 c]
        #pragma unroll
        for (int i = t; i < 4096; i += 128) {
            int kk = i >> 6, col = i & 63;
            Ws[i] = (col < 32) ? Wrel[(kc + kk) * 32 + col]
                               : Wroot[(kc + kk) * 32 + (col - 32)];
        }
        // stage X chunk [128 node][64 k], coalesced float4
        #pragma unroll
        for (int j = 0; j < 16; j++) {
            int idx  = t + 128 * j;          // 0..2047 float4 slots
            int kq   = idx & 15;
            int node = idx >> 4;
            int gn   = n0 + node;
            float4 v = (gn < N) ? *(const float4*)&x[gn * 128 + kc + kq * 4]
                                : make_float4(0.f, 0.f, 0.f, 0.f);
            float* dst = &Xs[node * XPITCH + kq * 4];
            dst[0] = v.x; dst[1] = v.y; dst[2] = v.z; dst[3] = v.w;
        }
        __syncthreads();

        const float* xrow = &Xs[(ty * 8) * XPITCH];
        #pragma unroll 2
        for (int kk = 0; kk < 64; kk += 2) {
            ulonglong2 a01 = *(const ulonglong2*)&Ws[kk * 64 + tx * 8];
            ulonglong2 a23 = *(const ulonglong2*)&Ws[kk * 64 + tx * 8 + 4];
            ulonglong2 b01 = *(const ulonglong2*)&Ws[(kk + 1) * 64 + tx * 8];
            ulonglong2 b23 = *(const ulonglong2*)&Ws[(kk + 1) * 64 + tx * 8 + 4];
            #pragma unroll
            for (int i = 0; i < 8; i++) {
                float2 xp = *(const float2*)&xrow[i * XPITCH + kk];
                unsigned long long ax = dup2(xp.x);
                unsigned long long ay = dup2(xp.y);
                ffma2(acc[i][0], ax, a01.x);
                ffma2(acc[i][1], ax, a01.y);
                ffma2(acc[i][2], ax, a23.x);
                ffma2(acc[i][3], ax, a23.y);
                ffma2(acc[i][0], ay, b01.x);
                ffma2(acc[i][1], ay, b01.y);
                ffma2(acc[i][2], ay, b23.x);
                ffma2(acc[i][3], ay, b23.y);
            }
        }
        __syncthreads();
    }

    #pragma unroll
    for (int i = 0; i < 8; i++) {
        int node = n0 + ty * 8 + i;
        if (node < N) {
            float2 p0 = u2f2(acc[i][0]), p1 = u2f2(acc[i][1]);
            float2 p2 = u2f2(acc[i][2]), p3 = u2f2(acc[i][3]);
            *(float4*)&g_xw[node * 64 + tx * 8]     = make_float4(p0.x, p0.y, p1.x, p1.y);
            *(float4*)&g_xw[node * 64 + tx * 8 + 4] = make_float4(p2.x, p2.y, p3.x, p3.y);
        }
    }
}

// ---- edge pass 1 (weighted): 8 threads/edge, LDG.128 + RED.128 ----
__global__ void __launch_bounds__(256) k_edge1(const float* __restrict__ ew, int E) {
    int t = blockIdx.x * 256 + threadIdx.x;
    int e = t >> 3, p = t & 7;
    if (e >= E) return;
    int s = g_src[e];
    int d = g_dst[e];
    float w = ew[e];
    float4 v = *(const float4*)&g_xw[s * 64 + p * 4];   // rel-projected cols 0..31
    v.x *= w; v.y *= w; v.z *= w; v.w *= w;
    red_add4(&g_sum1[d * 32 + p * 4], v);
}

// ---- combine layer 1 + project layer 2 ----
__global__ void __launch_bounds__(256) k_comb1(
    const float* __restrict__ b1,
    const float* __restrict__ Wrel2,    // [32][5]
    const float* __restrict__ Wroot2,   // [32][5]
    int N)
{
    __shared__ float sW[352];
    int t = threadIdx.x;
    for (int i = t; i < 352; i += 256) {
        sW[i] = (i < 160) ? Wrel2[i]
              : (i < 320) ? Wroot2[i - 160]
                          : b1[i - 320];
    }
    __syncthreads();

    int node = blockIdx.x * 256 + t;
    if (node >= N) return;

    float inv = 1.0f / fmaxf(g_cnt[node], 1.0f);
    const float4* sp = (const float4*)&g_sum1[node * 32];
    const float4* rp = (const float4*)&g_xw[node * 64 + 32];

    float h[32];
    #pragma unroll
    for (int q = 0; q < 8; q++) {
        float4 s4 = sp[q];
        float4 r4 = rp[q];
        h[4 * q + 0] = fmaxf(s4.x * inv + r4.x + sW[320 + 4 * q + 0], 0.f);
        h[4 * q + 1] = fmaxf(s4.y * inv + r4.y + sW[320 + 4 * q + 1], 0.f);
        h[4 * q + 2] = fmaxf(s4.z * inv + r4.z + sW[320 + 4 * q + 2], 0.f);
        h[4 * q + 3] = fmaxf(s4.w * inv + r4.w + sW[320 + 4 * q + 3], 0.f);
    }

    float hr[5] = {0.f, 0.f, 0.f, 0.f, 0.f};
    float ho[5] = {0.f, 0.f, 0.f, 0.f, 0.f};
    #pragma unroll
    for (int j = 0; j < 32; j++) {
        float hv = h[j];
        #pragma unroll
        for (int c = 0; c < 5; c++) {
            hr[c] += hv * sW[j * 5 + c];
            ho[c] += hv * sW[160 + j * 5 + c];
        }
    }
    *(float4*)&g_hr[node * 8 + 0]    = make_float4(hr[0], hr[1], hr[2], hr[3]);
    *(float4*)&g_hr[node * 8 + 4]    = make_float4(hr[4], 0.f, 0.f, 0.f);
    *(float4*)&g_hroot[node * 8 + 0] = make_float4(ho[0], ho[1], ho[2], ho[3]);
    *(float4*)&g_hroot[node * 8 + 4] = make_float4(ho[4], 0.f, 0.f, 0.f);
}

// ---- edge pass 2: 2 threads/edge, LDG.128 + RED.128 (cols 5..7 zero-pad) ----
__global__ void __launch_bounds__(256) k_edge2(int E) {
    int t = blockIdx.x * 256 + threadIdx.x;
    int e = t >> 1, p = t & 1;
    if (e >= E) return;
    int s = g_src[e];
    int d = g_dst[e];
    float4 v = *(const float4*)&g_hr[s * 8 + p * 4];
    red_add4(&g_sum2[d * 8 + p * 4], v);
}

// ---- combine layer 2 + log_softmax ----
__global__ void __launch_bounds__(256) k_final(
    const float* __restrict__ b2,
    float* __restrict__ out,
    int N)
{
    int node = blockIdx.x * 256 + threadIdx.x;
    if (node >= N) return;
    float inv = 1.0f / fmaxf(g_cnt[node], 1.0f);
    float v[5];
    #pragma unroll
    for (int c = 0; c < 5; c++)
        v[c] = g_sum2[node * 8 + c] * inv + g_hroot[node * 8 + c] + b2[c];

    float m = v[0];
    #pragma unroll
    for (int c = 1; c < 5; c++) m = fmaxf(m, v[c]);
    float sum = 0.f;
    #pragma unroll
    for (int c = 0; c < 5; c++) sum += expf(v[c] - m);
    float lse = m + logf(sum);
    #pragma unroll
    for (int c = 0; c < 5; c++) out[node * 5 + c] = v[c] - lse;
}

extern "C" void kernel_launch(void* const* d_in, const int* in_sizes, int n_in,
                              void* d_out, int out_size)
{
    const float* x      = (const float*)d_in[0];
    const int*   ei     = (const int*)d_in[1];
    const float* ew     = (const float*)d_in[2];
    const float* Wrel1  = (const float*)d_in[3];
    const float* Wroot1 = (const float*)d_in[4];
    const float* b1     = (const float*)d_in[5];
    const float* Wrel2  = (const float*)d_in[6];
    const float* Wroot2 = (const float*)d_in[7];
    const float* b2     = (const float*)d_in[8];
    float*       out    = (float*)d_out;

    int N = out_size / 5;          // output [N,5]
    int E = in_sizes[1] / 2;       // edge_index [2,E]

    const int GEMM_SMEM = (4096 + 128 * XPITCH) * 4;   // 53248 B
    cudaFuncSetAttribute(k_gemm1, cudaFuncAttributeMaxDynamicSharedMemorySize, GEMM_SMEM);

    k_detect<<<1, 64>>>(ei);
    k_zero  <<<1024, 256>>>(N);
    k_unpack<<<(E + 255) / 256, 256>>>(ei, E, N);
    k_gemm1 <<<(N + 127) / 128, 128, GEMM_SMEM>>>(x, Wrel1, Wroot1, N);
    k_edge1 <<<(E * 8 + 255) / 256, 256>>>(ew, E);
    k_comb1 <<<(N + 255) / 256, 256>>>(b1, Wrel2, Wroot2, N);
    k_edge2 <<<(E * 2 + 255) / 256, 256>>>(E);
    k_final <<<(N + 255) / 256, 256>>>(b2, out, N);
}